// round 11
// baseline (speedup 1.0000x reference)
#include <cuda_runtime.h>
#include <cuda_fp16.h>
#include <cstddef>
#include <cstdint>

#define BB 64
#define NN 2048
#define II 16
#define JJ 32
#define OO 32
#define JO 1024      // J*O
#define NB 8         // n's per stage/round in pass_kernel (== #warps)
#define CHUNK 128    // n's per pass CTA (16 chunks)
#define NROUND 16    // CHUNK / NB
#define STAGE_BYTES (NB * JO * 2)   // 16 KB
#define PASS_DYN_SMEM (3 * STAGE_BYTES + 4096 + 1024)
#define NCH0 32      // sum0 chunks
#define CH0 64       // n's per sum0 CTA
#define S0_STAGE (8 * 128 * 16)     // 16 KB
#define XPAD 20
#define PRED_DYN_SMEM (64 * 1024 + BB * XPAD * 4)   // w 65536 + x 5120

// Scratch (allocation-free rule: __device__ globals).
__device__ __half g_predh[(size_t)BB * NN * JO];        // 256 MB fp16 predictions
__device__ float g_pA[(size_t)NCH0 * BB * JO];          // partial buffer A (8 MB)
__device__ float g_pB[(size_t)16 * BB * JO];            // partial buffer B (4 MB)
__device__ float g_v[BB * JO];                          // squashed v
__device__ float g_blog[(size_t)BB * NN * JJ];          // routing logits (pass1 -> pass2)

__device__ __forceinline__ float4 h4_to_f4(uint2 u) {
    __half2 h0 = *reinterpret_cast<__half2*>(&u.x);
    __half2 h1 = *reinterpret_cast<__half2*>(&u.y);
    float2 a = __half22float2(h0);
    float2 c = __half22float2(h1);
    return make_float4(a.x, a.y, c.x, c.y);
}
__device__ __forceinline__ uint32_t f2tf32(float f) {
    uint32_t r;
    asm("cvt.rna.tf32.f32 %0, %1;" : "=r"(r) : "f"(f));
    return r;
}

// ---------------------------------------------------------------------------
// K1: predictions via tf32 mma.sync.m16n8k8. One CTA per n, 256 threads.
// C[64 b x 1024 jo] = x[64 x 16] * w[n]^T, K=16 = 2 k-steps.
// w staged by cp.async directly into B-fragment tile layout:
//   (jo, i-quad q) 16B chunk -> smem f32 addr (jo>>3)*128 + q*32 + (jo&7)*4.
// x staged into pad-20 rows (conflict-free A-frag LDS).
// Warp w owns jo [128w, 128w+128): A-frags once (32 regs), 16 subtiles x
// (4 b-tiles x 2 k-steps) MMAs, half2 stores.
// ---------------------------------------------------------------------------
__global__ __launch_bounds__(256, 2)
void pred_kernel(const float* __restrict__ x, const float* __restrict__ w) {
    extern __shared__ __align__(16) unsigned char psm[];
    float* w_sm = reinterpret_cast<float*>(psm);            // 16384 f32
    float* x_sm = reinterpret_cast<float*>(psm + 65536);    // 64 rows pad 20

    const int n = blockIdx.x;
    const int t = threadIdx.x;
    const int warp = t >> 5, lane = t & 31;

    // ---- stage w (tile layout) + x via cp.async ----
    {
        const float* wsrc = w + (size_t)n * (JO * II);
        uint32_t wdst = (uint32_t)__cvta_generic_to_shared(w_sm);
#pragma unroll
        for (int it = 0; it < 16; ++it) {
            int idx = it * 256 + t;          // chunk id: 1024 jo x 4 quads
            int jo = idx >> 2, q = idx & 3;
            uint32_t d = wdst + 4u * ((jo >> 3) * 128 + q * 32 + (jo & 7) * 4);
            asm volatile("cp.async.cg.shared.global [%0], [%1], 16;"
                         :: "r"(d), "l"(wsrc + jo * 16 + q * 4));
        }
        uint32_t xdst = (uint32_t)__cvta_generic_to_shared(x_sm);
        int b = t >> 2, q = t & 3;
        uint32_t d = xdst + 4u * (b * XPAD + q * 4);
        asm volatile("cp.async.cg.shared.global [%0], [%1], 16;"
                     :: "r"(d), "l"(x + ((size_t)b * NN + n) * II + q * 4));
        asm volatile("cp.async.commit_group;");
        asm volatile("cp.async.wait_group 0;");
    }
    __syncthreads();

    // ---- A fragments: 4 b-tiles x 2 k-steps x 4 regs ----
    uint32_t A[4][2][4];
    {
        const int r = lane >> 2, c = lane & 3;
#pragma unroll
        for (int bt = 0; bt < 4; ++bt)
#pragma unroll
            for (int ks = 0; ks < 2; ++ks) {
                A[bt][ks][0] = f2tf32(x_sm[(bt * 16 + r) * XPAD + ks * 8 + c]);
                A[bt][ks][1] = f2tf32(x_sm[(bt * 16 + r + 8) * XPAD + ks * 8 + c]);
                A[bt][ks][2] = f2tf32(x_sm[(bt * 16 + r) * XPAD + ks * 8 + c + 4]);
                A[bt][ks][3] = f2tf32(x_sm[(bt * 16 + r + 8) * XPAD + ks * 8 + c + 4]);
            }
    }

    __half* op = g_predh + (size_t)n * JO + warp * 128 + 2 * (lane & 3);
    const size_t bstr = (size_t)NN * JO;
    const int brow = lane >> 2;

    for (int s = 0; s < 16; ++s) {
        // B frags: conflict-free LDS (lane l reads blk*128 + {0,32,64,96} + l)
        const float* wb = w_sm + (warp * 16 + s) * 128 + lane;
        uint32_t B0 = f2tf32(wb[0]);    // kstep0, i 0-3
        uint32_t B1 = f2tf32(wb[32]);   // kstep0, i 4-7
        uint32_t B2 = f2tf32(wb[64]);   // kstep1, i 8-11
        uint32_t B3 = f2tf32(wb[96]);   // kstep1, i 12-15

        float acc[4][4];
#pragma unroll
        for (int bt = 0; bt < 4; ++bt) {
            acc[bt][0] = 0.f; acc[bt][1] = 0.f; acc[bt][2] = 0.f; acc[bt][3] = 0.f;
#pragma unroll
            for (int ks = 0; ks < 2; ++ks) {
                uint32_t bb0 = ks ? B2 : B0;
                uint32_t bb1 = ks ? B3 : B1;
                asm volatile(
                    "mma.sync.aligned.m16n8k8.row.col.f32.tf32.tf32.f32 "
                    "{%0,%1,%2,%3}, {%4,%5,%6,%7}, {%8,%9}, {%0,%1,%2,%3};"
                    : "+f"(acc[bt][0]), "+f"(acc[bt][1]),
                      "+f"(acc[bt][2]), "+f"(acc[bt][3])
                    : "r"(A[bt][ks][0]), "r"(A[bt][ks][1]),
                      "r"(A[bt][ks][2]), "r"(A[bt][ks][3]),
                      "r"(bb0), "r"(bb1));
            }
        }
#pragma unroll
        for (int bt = 0; bt < 4; ++bt) {
            __half2 h01 = __floats2half2_rn(acc[bt][0], acc[bt][1]);
            __half2 h23 = __floats2half2_rn(acc[bt][2], acc[bt][3]);
            __half* pp = op + s * 8;
            *reinterpret_cast<__half2*>(pp + (size_t)(bt * 16 + brow) * bstr) = h01;
            *reinterpret_cast<__half2*>(pp + (size_t)(bt * 16 + brow + 8) * bstr) = h23;
        }
    }
}

// ---------------------------------------------------------------------------
// K2: iter-0 s partials. Barrier-free per-thread 3-stage cp.async pipeline.
// ---------------------------------------------------------------------------
__global__ __launch_bounds__(128)
void sum0_kernel() {
    __shared__ __align__(16) unsigned char st[3][S0_STAGE];   // 48 KB
    const int chunk = blockIdx.x;   // 0..31
    const int b = blockIdx.y;
    const int t = threadIdx.x;      // octet index 0..127

    const char* gsrc = reinterpret_cast<const char*>(
        g_predh + ((size_t)b * NN + (size_t)chunk * CH0) * JO);
    const uint32_t sb0 = (uint32_t)__cvta_generic_to_shared(&st[0][0]);

    auto issue = [&](int s) {
        const char* g = gsrc + (size_t)s * S0_STAGE;
        uint32_t d = sb0 + (s % 3) * S0_STAGE;
#pragma unroll
        for (int k = 0; k < 8; ++k) {
            uint32_t off = (k * 128 + t) * 16;
            asm volatile("cp.async.cg.shared.global [%0], [%1], 16;"
                         :: "r"(d + off), "l"(g + off));
        }
        asm volatile("cp.async.commit_group;");
    };

    issue(0); issue(1);
    float sacc[8];
#pragma unroll
    for (int e = 0; e < 8; ++e) sacc[e] = 0.f;

    for (int s = 0; s < 8; ++s) {
        if (s + 2 < 8) { issue(s + 2); asm volatile("cp.async.wait_group 2;"); }
        else if (s + 1 < 8) { asm volatile("cp.async.wait_group 1;"); }
        else { asm volatile("cp.async.wait_group 0;"); }

        const unsigned char* sp = &st[s % 3][0];
#pragma unroll
        for (int k = 0; k < 8; ++k) {
            uint4 r = *reinterpret_cast<const uint4*>(sp + (k * 128 + t) * 16);
            float2 f0 = __half22float2(*reinterpret_cast<__half2*>(&r.x));
            float2 f1 = __half22float2(*reinterpret_cast<__half2*>(&r.y));
            float2 f2 = __half22float2(*reinterpret_cast<__half2*>(&r.z));
            float2 f3 = __half22float2(*reinterpret_cast<__half2*>(&r.w));
            sacc[0] += f0.x; sacc[1] += f0.y; sacc[2] += f1.x; sacc[3] += f1.y;
            sacc[4] += f2.x; sacc[5] += f2.y; sacc[6] += f3.x; sacc[7] += f3.y;
        }
    }
    const float inv = 1.0f / 32.0f;
    float* dst = g_pA + ((size_t)chunk * BB + b) * JO + t * 8;
    reinterpret_cast<float4*>(dst)[0] =
        make_float4(sacc[0] * inv, sacc[1] * inv, sacc[2] * inv, sacc[3] * inv);
    reinterpret_cast<float4*>(dst)[1] =
        make_float4(sacc[4] * inv, sacc[5] * inv, sacc[6] * inv, sacc[7] * inv);
}

// ---------------------------------------------------------------------------
// K3: reduce partials + squash -> g_v (and optionally d_out).
// ---------------------------------------------------------------------------
template <int NCHIN, bool INA>
__global__ __launch_bounds__(1024)
void v_kernel(float* __restrict__ out) {
    const float* pin = INA ? g_pA : g_pB;
    const int b = blockIdx.x;
    const int t = threadIdx.x;
    float s = 0.f;
#pragma unroll
    for (int k = 0; k < NCHIN; ++k)
        s += pin[((size_t)k * BB + b) * JO + t];
    float sq = s * s;
#pragma unroll
    for (int m = 16; m > 0; m >>= 1)
        sq += __shfl_xor_sync(0xffffffffu, sq, m);
    float scale = (sq / (1.0f + sq)) * rsqrtf(sq + 1e-8f);
    float v = s * scale;
    g_v[b * JO + t] = v;
    if (out) out[b * JO + t] = v;
}

// ---------------------------------------------------------------------------
// K4: routing pass (iters 1,2) with 3-stage cp.async ring (R10 winner).
// ---------------------------------------------------------------------------
template <int MODE, bool OUTA>
__global__ __launch_bounds__(256)
void pass_kernel() {
    extern __shared__ __align__(16) unsigned char dyn[];
    float (*a_part)[JJ][4] = reinterpret_cast<float(*)[JJ][4]>(dyn + 3 * STAGE_BYTES);
    float (*c_buf)[JJ] = reinterpret_cast<float(*)[JJ]>(dyn + 3 * STAGE_BYTES + 4096);

    const int chunk = blockIdx.x;
    const int b = blockIdx.y;
    const int t = threadIdx.x;
    const int warp = t >> 5;
    const int lane = t & 31;
    const int j = t >> 3;
    const int sub = t & 7;

    const float4 vv = reinterpret_cast<const float4*>(g_v + b * JO)[t];
    float4 sacc = make_float4(0.f, 0.f, 0.f, 0.f);

    const char* gsrc = reinterpret_cast<const char*>(
        g_predh + ((size_t)b * NN + (size_t)chunk * CHUNK) * JO);
    const uint32_t sb0 = (uint32_t)__cvta_generic_to_shared(dyn);

    auto issue = [&](int r) {
        const char* g = gsrc + (size_t)r * STAGE_BYTES;
        uint32_t d = sb0 + (r % 3) * STAGE_BYTES;
#pragma unroll
        for (int i = 0; i < 4; ++i) {
            uint32_t off = (i * 256 + t) * 16;
            asm volatile("cp.async.cg.shared.global [%0], [%1], 16;"
                         :: "r"(d + off), "l"(g + off));
        }
        asm volatile("cp.async.commit_group;");
    };

    issue(0); issue(1);

    for (int r = 0; r < NROUND; ++r) {
        if (r + 2 < NROUND) { issue(r + 2); asm volatile("cp.async.wait_group 2;"); }
        else if (r + 1 < NROUND) { asm volatile("cp.async.wait_group 1;"); }
        else { asm volatile("cp.async.wait_group 0;"); }
        __syncthreads();

        const uint32_t sb = sb0 + (r % 3) * STAGE_BYTES;

#pragma unroll
        for (int k = 0; k < NB; ++k) {
            uint2 u;
            asm("ld.shared.v2.u32 {%0, %1}, [%2];"
                : "=r"(u.x), "=r"(u.y) : "r"(sb + k * (JO * 2) + t * 8));
            float4 p = h4_to_f4(u);
            float d = p.x * vv.x + p.y * vv.y + p.z * vv.z + p.w * vv.w;
            d += __shfl_xor_sync(0xffffffffu, d, 4);
            if (sub < 4) a_part[k][j][sub] = d;
        }
        __syncthreads();

        {
            const int k = warp;
            const int n = chunk * CHUNK + r * NB + k;
            float4 q = *reinterpret_cast<const float4*>(&a_part[k][lane][0]);
            float a = (q.x + q.y) + (q.z + q.w);
            size_t bidx = ((size_t)b * NN + n) * JJ + lane;
            if (MODE == 2) a += g_blog[bidx];
            else           g_blog[bidx] = a;
            float m = a;
#pragma unroll
            for (int s = 16; s > 0; s >>= 1)
                m = fmaxf(m, __shfl_xor_sync(0xffffffffu, m, s));
            float e = __expf(a - m);
            float ssum = e;
#pragma unroll
            for (int s = 16; s > 0; s >>= 1)
                ssum += __shfl_xor_sync(0xffffffffu, ssum, s);
            c_buf[k][lane] = e / ssum;
        }
        __syncthreads();

#pragma unroll
        for (int k = 0; k < NB; ++k) {
            float c = c_buf[k][j];
            uint2 u;
            asm("ld.shared.v2.u32 {%0, %1}, [%2];"
                : "=r"(u.x), "=r"(u.y) : "r"(sb + k * (JO * 2) + t * 8));
            float4 p = h4_to_f4(u);
            sacc.x = fmaf(c, p.x, sacc.x);
            sacc.y = fmaf(c, p.y, sacc.y);
            sacc.z = fmaf(c, p.z, sacc.z);
            sacc.w = fmaf(c, p.w, sacc.w);
        }
        __syncthreads();
    }

    float* pout = OUTA ? g_pA : g_pB;
    reinterpret_cast<float4*>(pout + ((size_t)chunk * BB + b) * JO)[t] = sacc;
}

// ---------------------------------------------------------------------------
extern "C" void kernel_launch(void* const* d_in, const int* in_sizes, int n_in,
                              void* d_out, int out_size) {
    const float* x = (const float*)d_in[0];   // [64, 2048, 16] f32
    const float* w = (const float*)d_in[1];   // [2048, 32, 32, 16] f32
    float* out = (float*)d_out;               // [64, 32, 32] f32

    cudaFuncSetAttribute(pred_kernel,
                         cudaFuncAttributeMaxDynamicSharedMemorySize, PRED_DYN_SMEM);
    cudaFuncSetAttribute(pass_kernel<1, false>,
                         cudaFuncAttributeMaxDynamicSharedMemorySize, PASS_DYN_SMEM);
    cudaFuncSetAttribute(pass_kernel<2, true>,
                         cudaFuncAttributeMaxDynamicSharedMemorySize, PASS_DYN_SMEM);

    pred_kernel<<<NN, 256, PRED_DYN_SMEM>>>(x, w);
    sum0_kernel<<<dim3(NCH0, BB), 128>>>();                      // s0 -> A (32)
    v_kernel<NCH0, true><<<BB, 1024>>>(nullptr);                 // v0
    pass_kernel<1, false><<<dim3(16, BB), 256, PASS_DYN_SMEM>>>();  // s1 -> B
    v_kernel<16, false><<<BB, 1024>>>(nullptr);                  // v1
    pass_kernel<2, true><<<dim3(16, BB), 256, PASS_DYN_SMEM>>>();   // s2 -> A
    v_kernel<16, true><<<BB, 1024>>>(out);                       // v2 -> output
}

// round 12
// speedup vs baseline: 1.5732x; 1.5732x over previous
#include <cuda_runtime.h>
#include <cuda_fp16.h>
#include <cstddef>
#include <cstdint>

#define BB 64
#define NN 2048
#define II 16
#define JJ 32
#define OO 32
#define JO 1024      // J*O
#define NB 8         // n's per stage/round in pass_kernel (== #warps)
#define CHUNK 128    // n's per pass CTA (16 chunks)
#define NROUND 16    // CHUNK / NB
#define STAGE_BYTES (NB * JO * 2)   // 16 KB
#define PASS_DYN_SMEM (3 * STAGE_BYTES + 4096 + 1024)
#define NCH0 32      // sum0 chunks
#define CH0 64       // n's per sum0 CTA
#define S0_STAGE (8 * 128 * 16)     // 16 KB

// Scratch (allocation-free rule: __device__ globals).
__device__ __half g_predh[(size_t)BB * NN * JO];        // 256 MB fp16 predictions
__device__ float g_pA[(size_t)NCH0 * BB * JO];          // partial buffer A (8 MB)
__device__ float g_pB[(size_t)16 * BB * JO];            // partial buffer B (4 MB)
__device__ float g_blog[(size_t)BB * NN * JJ];          // routing logits (pass1 -> pass2)

// ---- packed fp32x2 helpers (sm_103a) --------------------------------------
__device__ __forceinline__ unsigned long long pk2(float a, float b) {
    unsigned long long r;
    asm("mov.b64 %0, {%1, %2};" : "=l"(r) : "f"(a), "f"(b));
    return r;
}
__device__ __forceinline__ void ffma2(unsigned long long& d,
                                      unsigned long long a,
                                      unsigned long long b) {
    asm("fma.rn.f32x2 %0, %1, %2, %0;" : "+l"(d) : "l"(a), "l"(b));
}
__device__ __forceinline__ unsigned long long add2(unsigned long long a,
                                                   unsigned long long b) {
    unsigned long long r;
    asm("add.rn.f32x2 %0, %1, %2;" : "=l"(r) : "l"(a), "l"(b));
    return r;
}
__device__ __forceinline__ float2 up2(unsigned long long v) {
    float2 f;
    asm("mov.b64 {%0, %1}, %2;" : "=f"(f.x), "=f"(f.y) : "l"(v));
    return f;
}
__device__ __forceinline__ float4 h4_to_f4(uint2 u) {
    __half2 h0 = *reinterpret_cast<__half2*>(&u.x);
    __half2 h1 = *reinterpret_cast<__half2*>(&u.y);
    float2 a = __half22float2(h0);
    float2 c = __half22float2(h1);
    return make_float4(a.x, a.y, c.x, c.y);
}

// ---------------------------------------------------------------------------
// K1: predictions via packed f32x2 FFMA, 4 independent accumulator chains
// (R10 version — best known). One CTA per n, 256 threads; thread t owns jo
// [4t,4t+4). Weight pairs packed once; x duplicated (x,x) in smem.
// ---------------------------------------------------------------------------
__global__ __launch_bounds__(256, 2)
void pred_kernel(const float* __restrict__ x, const float* __restrict__ w) {
    const int n = blockIdx.x;
    const int t = threadIdx.x;

    __shared__ float2 xs2[BB][II];   // (x,x) duplicated pairs, 8 KB
    {
        int b = t >> 2, q = t & 3;
        float4 f = reinterpret_cast<const float4*>(x + ((size_t)b * NN + n) * II)[q];
        xs2[b][4 * q + 0] = make_float2(f.x, f.x);
        xs2[b][4 * q + 1] = make_float2(f.y, f.y);
        xs2[b][4 * q + 2] = make_float2(f.z, f.z);
        xs2[b][4 * q + 3] = make_float2(f.w, f.w);
    }

    float wr[4][16];
    const float4* wp = reinterpret_cast<const float4*>(w + ((size_t)n * JO + 4 * t) * II);
#pragma unroll
    for (int q = 0; q < 4; ++q) {
#pragma unroll
        for (int c = 0; c < 4; ++c) {
            float4 f = wp[q * 4 + c];
            wr[q][4 * c + 0] = f.x; wr[q][4 * c + 1] = f.y;
            wr[q][4 * c + 2] = f.z; wr[q][4 * c + 3] = f.w;
        }
    }
    unsigned long long wp01[16], wp23[16];
#pragma unroll
    for (int i = 0; i < 16; ++i) {
        wp01[i] = pk2(wr[0][i], wr[1][i]);
        wp23[i] = pk2(wr[2][i], wr[3][i]);
    }
    __syncthreads();

    __half* outp = g_predh + (size_t)n * JO + 4 * t;
    uint32_t xbase = (uint32_t)__cvta_generic_to_shared(&xs2[0][0]);

#pragma unroll 4
    for (int b = 0; b < BB; ++b) {
        uint32_t xa = xbase + b * (II * 8);
        unsigned long long a0 = 0ull, a1 = 0ull, a2 = 0ull, a3 = 0ull;
#pragma unroll
        for (int k = 0; k < 8; ++k) {
            unsigned long long xx0, xx1;
            asm("ld.shared.v2.u64 {%0, %1}, [%2];"
                : "=l"(xx0), "=l"(xx1) : "r"(xa + k * 16));
            ffma2(a0, xx0, wp01[2 * k]);
            ffma2(a1, xx1, wp01[2 * k + 1]);
            ffma2(a2, xx0, wp23[2 * k]);
            ffma2(a3, xx1, wp23[2 * k + 1]);
        }
        float2 a01 = up2(add2(a0, a1));
        float2 a23 = up2(add2(a2, a3));
        __half2 b01 = __float22half2_rn(a01);
        __half2 b23 = __float22half2_rn(a23);
        uint2 st;
        st.x = *reinterpret_cast<unsigned int*>(&b01);
        st.y = *reinterpret_cast<unsigned int*>(&b23);
        *reinterpret_cast<uint2*>(outp + (size_t)b * NN * JO) = st;
    }
}

// ---------------------------------------------------------------------------
// K2: iter-0 s partials. Barrier-free per-thread 3-stage cp.async pipeline
// (R10 version). 128 threads; thread t owns jo octet [8t, 8t+8).
// ---------------------------------------------------------------------------
__global__ __launch_bounds__(128)
void sum0_kernel() {
    __shared__ __align__(16) unsigned char st[3][S0_STAGE];   // 48 KB
    const int chunk = blockIdx.x;   // 0..31
    const int b = blockIdx.y;
    const int t = threadIdx.x;      // octet index 0..127

    const char* gsrc = reinterpret_cast<const char*>(
        g_predh + ((size_t)b * NN + (size_t)chunk * CH0) * JO);
    const uint32_t sb0 = (uint32_t)__cvta_generic_to_shared(&st[0][0]);

    auto issue = [&](int s) {
        const char* g = gsrc + (size_t)s * S0_STAGE;
        uint32_t d = sb0 + (s % 3) * S0_STAGE;
#pragma unroll
        for (int k = 0; k < 8; ++k) {
            uint32_t off = (k * 128 + t) * 16;
            asm volatile("cp.async.cg.shared.global [%0], [%1], 16;"
                         :: "r"(d + off), "l"(g + off));
        }
        asm volatile("cp.async.commit_group;");
    };

    issue(0); issue(1);
    float sacc[8];
#pragma unroll
    for (int e = 0; e < 8; ++e) sacc[e] = 0.f;

    for (int s = 0; s < 8; ++s) {
        if (s + 2 < 8) { issue(s + 2); asm volatile("cp.async.wait_group 2;"); }
        else if (s + 1 < 8) { asm volatile("cp.async.wait_group 1;"); }
        else { asm volatile("cp.async.wait_group 0;"); }

        const unsigned char* sp = &st[s % 3][0];
#pragma unroll
        for (int k = 0; k < 8; ++k) {
            uint4 r = *reinterpret_cast<const uint4*>(sp + (k * 128 + t) * 16);
            float2 f0 = __half22float2(*reinterpret_cast<__half2*>(&r.x));
            float2 f1 = __half22float2(*reinterpret_cast<__half2*>(&r.y));
            float2 f2 = __half22float2(*reinterpret_cast<__half2*>(&r.z));
            float2 f3 = __half22float2(*reinterpret_cast<__half2*>(&r.w));
            sacc[0] += f0.x; sacc[1] += f0.y; sacc[2] += f1.x; sacc[3] += f1.y;
            sacc[4] += f2.x; sacc[5] += f2.y; sacc[6] += f3.x; sacc[7] += f3.y;
        }
    }
    const float inv = 1.0f / 32.0f;
    float* dst = g_pA + ((size_t)chunk * BB + b) * JO + t * 8;
    reinterpret_cast<float4*>(dst)[0] =
        make_float4(sacc[0] * inv, sacc[1] * inv, sacc[2] * inv, sacc[3] * inv);
    reinterpret_cast<float4*>(dst)[1] =
        make_float4(sacc[4] * inv, sacc[5] * inv, sacc[6] * inv, sacc[7] * inv);
}

// ---------------------------------------------------------------------------
// K3: final reduce + squash -> d_out (only one launch remains).
// ---------------------------------------------------------------------------
template <int NCHIN, bool INA>
__global__ __launch_bounds__(1024)
void v_kernel(float* __restrict__ out) {
    const float* pin = INA ? g_pA : g_pB;
    const int b = blockIdx.x;
    const int t = threadIdx.x;
    float s = 0.f;
#pragma unroll
    for (int k = 0; k < NCHIN; ++k)
        s += pin[((size_t)k * BB + b) * JO + t];
    float sq = s * s;
#pragma unroll
    for (int m = 16; m > 0; m >>= 1)
        sq += __shfl_xor_sync(0xffffffffu, sq, m);
    float scale = (sq / (1.0f + sq)) * rsqrtf(sq + 1e-8f);
    out[b * JO + t] = s * scale;
}

// ---------------------------------------------------------------------------
// K4: routing pass (iters 1,2), R10 3-stage cp.async ring + in-register v
// prologue (deletes the separate v0/v1 kernels). Each thread reduces its own
// jo-quad over NCHIN partial chunks (L2-resident; overlaps the stage-0/1
// fills), 8-lane shuffle for |s|^2, squash -> vv in 4 regs. Reads the
// opposite partial buffer from the one it writes (no cross-CTA races).
//   MODE 1: a = pred.v,  blog = a, softmax(a)
//   MODE 2: a = blog + pred.v,    softmax(a)
// ---------------------------------------------------------------------------
template <int MODE, bool OUTA, int NCHIN>
__global__ __launch_bounds__(256, 4)
void pass_kernel() {
    extern __shared__ __align__(16) unsigned char dyn[];
    float (*a_part)[JJ][4] = reinterpret_cast<float(*)[JJ][4]>(dyn + 3 * STAGE_BYTES);
    float (*c_buf)[JJ] = reinterpret_cast<float(*)[JJ]>(dyn + 3 * STAGE_BYTES + 4096);

    const int chunk = blockIdx.x;
    const int b = blockIdx.y;
    const int t = threadIdx.x;
    const int warp = t >> 5;
    const int lane = t & 31;
    const int j = t >> 3;
    const int sub = t & 7;

    const char* gsrc = reinterpret_cast<const char*>(
        g_predh + ((size_t)b * NN + (size_t)chunk * CHUNK) * JO);
    const uint32_t sb0 = (uint32_t)__cvta_generic_to_shared(dyn);

    auto issue = [&](int r) {
        const char* g = gsrc + (size_t)r * STAGE_BYTES;
        uint32_t d = sb0 + (r % 3) * STAGE_BYTES;
#pragma unroll
        for (int i = 0; i < 4; ++i) {
            uint32_t off = (i * 256 + t) * 16;
            asm volatile("cp.async.cg.shared.global [%0], [%1], 16;"
                         :: "r"(d + off), "l"(g + off));
        }
        asm volatile("cp.async.commit_group;");
    };

    issue(0); issue(1);

    // ---- prologue: s from partials (opposite buffer), squash -> vv regs ----
    float4 vv;
    {
        const float* pin = OUTA ? g_pB : g_pA;
        float4 sv = make_float4(0.f, 0.f, 0.f, 0.f);
#pragma unroll
        for (int k = 0; k < NCHIN; ++k) {
            float4 p = reinterpret_cast<const float4*>(
                pin + ((size_t)k * BB + b) * JO)[t];
            sv.x += p.x; sv.y += p.y; sv.z += p.z; sv.w += p.w;
        }
        float sq = sv.x * sv.x + sv.y * sv.y + sv.z * sv.z + sv.w * sv.w;
        sq += __shfl_xor_sync(0xffffffffu, sq, 1);
        sq += __shfl_xor_sync(0xffffffffu, sq, 2);
        sq += __shfl_xor_sync(0xffffffffu, sq, 4);
        float scale = (sq / (1.0f + sq)) * rsqrtf(sq + 1e-8f);
        vv = make_float4(sv.x * scale, sv.y * scale, sv.z * scale, sv.w * scale);
    }

    float4 sacc = make_float4(0.f, 0.f, 0.f, 0.f);

    for (int r = 0; r < NROUND; ++r) {
        if (r + 2 < NROUND) { issue(r + 2); asm volatile("cp.async.wait_group 2;"); }
        else if (r + 1 < NROUND) { asm volatile("cp.async.wait_group 1;"); }
        else { asm volatile("cp.async.wait_group 0;"); }
        __syncthreads();

        const uint32_t sb = sb0 + (r % 3) * STAGE_BYTES;

        // phase A: partial dots, one pre-reduce shuffle, half-lanes write
#pragma unroll
        for (int k = 0; k < NB; ++k) {
            uint2 u;
            asm("ld.shared.v2.u32 {%0, %1}, [%2];"
                : "=r"(u.x), "=r"(u.y) : "r"(sb + k * (JO * 2) + t * 8));
            float4 p = h4_to_f4(u);
            float d = p.x * vv.x + p.y * vv.y + p.z * vv.z + p.w * vv.w;
            d += __shfl_xor_sync(0xffffffffu, d, 4);
            if (sub < 4) a_part[k][j][sub] = d;
        }
        __syncthreads();

        {   // phase B: warp k finishes dot for n = base+k, blog, softmax
            const int k = warp;
            const int n = chunk * CHUNK + r * NB + k;
            float4 q = *reinterpret_cast<const float4*>(&a_part[k][lane][0]);
            float a = (q.x + q.y) + (q.z + q.w);
            size_t bidx = ((size_t)b * NN + n) * JJ + lane;
            if (MODE == 2) a += g_blog[bidx];
            else           g_blog[bidx] = a;     // b1 = agreement (b0 = 0)
            float m = a;
#pragma unroll
            for (int s = 16; s > 0; s >>= 1)
                m = fmaxf(m, __shfl_xor_sync(0xffffffffu, m, s));
            float e = __expf(a - m);
            float ssum = e;
#pragma unroll
            for (int s = 16; s > 0; s >>= 1)
                ssum += __shfl_xor_sync(0xffffffffu, ssum, s);
            c_buf[k][lane] = e / ssum;
        }
        __syncthreads();

        // phase C: c-weighted accumulation (re-read pred from smem)
#pragma unroll
        for (int k = 0; k < NB; ++k) {
            float c = c_buf[k][j];
            uint2 u;
            asm("ld.shared.v2.u32 {%0, %1}, [%2];"
                : "=r"(u.x), "=r"(u.y) : "r"(sb + k * (JO * 2) + t * 8));
            float4 p = h4_to_f4(u);
            sacc.x = fmaf(c, p.x, sacc.x);
            sacc.y = fmaf(c, p.y, sacc.y);
            sacc.z = fmaf(c, p.z, sacc.z);
            sacc.w = fmaf(c, p.w, sacc.w);
        }
        __syncthreads();   // stage r free before round r+1 issues over it
    }

    float* pout = OUTA ? g_pA : g_pB;
    reinterpret_cast<float4*>(pout + ((size_t)chunk * BB + b) * JO)[t] = sacc;
}

// ---------------------------------------------------------------------------
extern "C" void kernel_launch(void* const* d_in, const int* in_sizes, int n_in,
                              void* d_out, int out_size) {
    const float* x = (const float*)d_in[0];   // [64, 2048, 16] f32
    const float* w = (const float*)d_in[1];   // [2048, 32, 32, 16] f32
    float* out = (float*)d_out;               // [64, 32, 32] f32

    cudaFuncSetAttribute(pass_kernel<1, false, NCH0>,
                         cudaFuncAttributeMaxDynamicSharedMemorySize, PASS_DYN_SMEM);
    cudaFuncSetAttribute(pass_kernel<2, true, 16>,
                         cudaFuncAttributeMaxDynamicSharedMemorySize, PASS_DYN_SMEM);

    pred_kernel<<<NN, 256>>>(x, w);
    sum0_kernel<<<dim3(NCH0, BB), 128>>>();                 // s0 partials -> A
    pass_kernel<1, false, NCH0>                             // v0 in-prologue,
        <<<dim3(16, BB), 256, PASS_DYN_SMEM>>>();           //   s1 -> B
    pass_kernel<2, true, 16>                                // v1 in-prologue,
        <<<dim3(16, BB), 256, PASS_DYN_SMEM>>>();           //   s2 -> A
    v_kernel<16, true><<<BB, 1024>>>(out);                  // v2 -> output
}